// round 6
// baseline (speedup 1.0000x reference)
#include <cuda_runtime.h>

#define NRAD  16
#define NL    2
#define NOUT  144            // 16*(1 + 2*4)
#define L35   35
#define KG    9              // 9 chunks of 4 k-values (36 padded)
#define HALFT 144            // threads per atom: 16 j x 9 kg
#define BLOCK 288            // 2 atoms per block -> 9 full warps
#define TCAP  64             // edges staged per tile
#define MAXNAT 4096

__device__ int g_segstart[MAXNAT + 1];

typedef unsigned long long ull;

__device__ __forceinline__ ull pack2(float x, float y) {
    ull r; asm("mov.b64 %0, {%1, %2};" : "=l"(r) : "f"(x), "f"(y)); return r;
}
__device__ __forceinline__ ull dup2(float x) {
    ull r; asm("mov.b64 %0, {%1, %1};" : "=l"(r) : "f"(x)); return r;
}
__device__ __forceinline__ void unpack2(ull p, float& x, float& y) {
    asm("mov.b64 {%0, %1}, %2;" : "=f"(x), "=f"(y) : "l"(p));
}
__device__ __forceinline__ void fma2(ull& d, ull a, ull b) {
    asm("fma.rn.f32x2 %0, %1, %2, %0;" : "+l"(d) : "l"(a), "l"(b));
}

__constant__ int   c_S [L35] = {0, 1,1,1, 2,2,2,2,2,2,
                                3,3,3,3,3,3,3,3,3,3,
                                4,4,4,4,4,4,4,4,4,4,4,4,4,4,4};
__constant__ int   c_LX[L35] = {0, 0,0,1, 0,0,0,1,1,2,
                                0,0,0,0,1,1,1,2,2,3,
                                0,0,0,0,0,1,1,1,1,2,2,2,3,3,4};
__constant__ int   c_LY[L35] = {0, 0,1,0, 0,1,2,0,1,0,
                                0,1,2,3,0,1,2,0,1,0,
                                0,1,2,3,4,0,1,2,3,0,1,2,0,1,0};
__constant__ int   c_LZ[L35] = {0, 1,0,0, 2,1,0,1,0,0,
                                3,2,1,0,2,1,0,1,0,0,
                                4,3,2,1,0,3,2,1,0,2,1,0,1,0,0};
__constant__ float c_FN[L35] = {1.f, 1.f,1.f,1.f,
                                1.f,2.f,1.f,2.f,2.f,1.f,
                                1.f,3.f,3.f,1.f,3.f,6.f,3.f,3.f,3.f,1.f,
                                1.f,4.f,6.f,4.f,1.f,4.f,12.f,12.f,4.f,
                                6.f,12.f,6.f,4.f,4.f,1.f};

// segstart[a] = first edge e with fidx[e] >= a (fidx sorted ascending)
__global__ __launch_bounds__(256)
void seg_kernel(const int* __restrict__ fidx, int E, int nat)
{
    int e = blockIdx.x * blockDim.x + threadIdx.x;
    if (e >= E) return;
    int cur  = fidx[e];
    int prev = (e == 0) ? -1 : fidx[e - 1];
    for (int a = prev + 1; a <= cur; a++) g_segstart[a] = e;
    if (e == E - 1)
        for (int a = cur + 1; a <= nat; a++) g_segstart[a] = E;
}

__global__ __launch_bounds__(BLOCK, 5)
void mbp_main(const float* __restrict__ radial,   // [E,16,5]
              const float* __restrict__ rij,      // [E,3]
              const float* __restrict__ lamw,     // [NL]
              float* __restrict__ out,            // [nat, NOUT]
              int nat)
{
    __shared__ __align__(16) float s_r [TCAP * 80];   // staged radial rows
    __shared__ __align__(16) float s_g [TCAP * 36];   // monomials (k=35 pad 0)
    __shared__ float s_pw[TCAP][3][5];                 // v^0..v^4
    __shared__ float s_lam[NL][36];
    __shared__ float s_part[2][KG][NRAD][8];

    const int tid  = threadIdx.x;
    const int half = (tid >= HALFT) ? 1 : 0;
    const int t    = tid - half * HALFT;
    const int j    = t & 15;        // 0..15 radial index
    const int kg   = t >> 4;        // 0..8  angular chunk
    const int k0   = kg * 4;
    const int a    = blockIdx.x * 2 + half;

    if (tid < NL * 36) {
        int l = (tid >= 36) ? 1 : 0;
        int k = tid - l * 36;
        float p = 0.f;
        if (k < L35) {
            float b = lamw[l];
            int   s = c_S[k];
            p = 1.f;                       // exact integer power (b may be < 0)
            for (int i = 0; i < s; i++) p *= b;
        }
        s_lam[l][k] = p;
    }

    const int a0 = blockIdx.x * 2;
    const int s0 = g_segstart[a0];
    const int e1 = g_segstart[min(a0 + 2, nat)];
    const int myS = (a < nat) ? g_segstart[a]     : 0;
    const int myE = (a < nat) ? g_segstart[a + 1] : 0;

    ull accA[4] = {0,0,0,0};        // (k0,k0+1) per channel-pair A=(c0,c1)... layout as R3
    ull accB[4] = {0,0,0,0};
    float accR = 0.f;

    for (int t0 = s0; t0 < e1; t0 += TCAP) {
        const int cnt = min(TCAP, e1 - t0);
        __syncthreads();                       // WAR vs previous tile reads

        // stage radial rows verbatim (coalesced float4)
        const float4* src = (const float4*)(radial + (size_t)t0 * 80);
        for (int i = tid; i < cnt * 20; i += BLOCK)
            ((float4*)s_r)[i] = src[i];
        // stage rij power tables
        for (int i = tid; i < cnt * 3; i += BLOCK) {
            int e = i / 3, c = i - e * 3;
            float v  = rij[(size_t)t0 * 3 + i];
            float v2 = v * v;
            s_pw[e][c][0] = 1.f;
            s_pw[e][c][1] = v;
            s_pw[e][c][2] = v2;
            s_pw[e][c][3] = v2 * v;
            s_pw[e][c][4] = v2 * v2;
        }
        __syncthreads();

        // angular monomials
        for (int i = tid; i < cnt * 36; i += BLOCK) {
            int e = i / 36, k = i - e * 36;
            float gv = 0.f;
            if (k < L35)
                gv = c_FN[k] * s_pw[e][0][c_LX[k]]
                             * s_pw[e][1][c_LY[k]]
                             * s_pw[e][2][c_LZ[k]];
            s_g[e * 36 + k] = gv;
        }
        __syncthreads();

        // hot loop: LDS-only rank-1 accumulation over this half's sub-range
        const int ls = max(myS, t0) - t0;
        const int le = min(myE, t0 + cnt) - t0;
        #pragma unroll 2
        for (int e = ls; e < le; e++) {
            const float* rp = &s_r[e * 80 + j * 5];   // stride-5: conflict-free
            float r0 = rp[0], r1 = rp[1], r2 = rp[2], r3 = rp[3];
            if (kg == 0) accR += rp[4];
            float4 g4 = *(const float4*)&s_g[e * 36 + k0];  // 144B*e + 16B*kg: aligned
            ull gA = pack2(g4.x, g4.y);
            ull gB = pack2(g4.z, g4.w);
            ull d0 = dup2(r0), d1 = dup2(r1), d2 = dup2(r2), d3 = dup2(r3);
            fma2(accA[0], gA, d0);  fma2(accB[0], gB, d0);
            fma2(accA[1], gA, d1);  fma2(accB[1], gB, d1);
            fma2(accA[2], gA, d2);  fma2(accB[2], gB, d2);
            fma2(accA[3], gA, d3);  fma2(accB[3], gB, d3);
        }
    }

    // per-thread partial lambda contraction over this thread's 4 k-values
    {
        float lv0[4], lv1[4];
        #pragma unroll
        for (int q = 0; q < 4; q++) {
            lv0[q] = s_lam[0][k0 + q];
            lv1[q] = s_lam[1][k0 + q];
        }
        // accA[c] holds (k0,k0+1) for channel c; accB[c] holds (k0+2,k0+3)
        float sq[4][4];                       // [c][q]
        #pragma unroll
        for (int c = 0; c < 4; c++) {
            float u, v;
            unpack2(accA[c], u, v);  sq[c][0] = u*u;  sq[c][1] = v*v;
            unpack2(accB[c], u, v);  sq[c][2] = u*u;  sq[c][3] = v*v;
        }
        __syncthreads();                      // all tile reads done (s_part aliasing-free anyway)
        #pragma unroll
        for (int c = 0; c < 4; c++) {
            float p0 = fmaf(sq[c][0], lv0[0], fmaf(sq[c][1], lv0[1],
                       fmaf(sq[c][2], lv0[2], sq[c][3] * lv0[3])));
            float p1 = fmaf(sq[c][0], lv1[0], fmaf(sq[c][1], lv1[1],
                       fmaf(sq[c][2], lv1[2], sq[c][3] * lv1[3])));
            s_part[half][kg][j][c*2 + 0] = p0;
            s_part[half][kg][j][c*2 + 1] = p1;
        }
    }
    if (kg == 0 && a < nat) out[(size_t)a * NOUT + j] = accR;
    __syncthreads();

    // reduce over kg groups: 256 outputs = 2 atoms x (j2, c, l)
    if (tid < 256) {
        int h2  = tid >> 7;
        int low = tid & 127;
        int co  = low & 7;           // c*2 + l
        int j2  = low >> 3;          // 0..15
        int ao  = blockIdx.x * 2 + h2;
        if (ao < nat) {
            float sum = 0.f;
            #pragma unroll
            for (int k = 0; k < KG; k++) sum += s_part[h2][k][j2][co];
            int c = co >> 1, l = co & 1;
            float scale = __int_as_float(0x3F800000 - (c << 23));   // 2^-c
            out[(size_t)ao * NOUT + NRAD + c*(NRAD*NL) + j2*NL + l] = sum * scale;
        }
    }
}

extern "C" void kernel_launch(void* const* d_in, const int* in_sizes, int n_in,
                              void* d_out, int out_size)
{
    const float* rij    = (const float*)d_in[0];   // [E,3]
    const float* radial = (const float*)d_in[1];   // [E,16,5]
    const float* lamw   = (const float*)d_in[2];   // [2]
    const int*   fidx   = (const int*)  d_in[4];   // [E] sorted

    const int E   = in_sizes[0] / 3;
    const int nat = out_size / NOUT;

    seg_kernel<<<(E + 255) / 256, 256>>>(fidx, E, nat);
    mbp_main  <<<(nat + 1) / 2, BLOCK>>>(radial, rij, lamw, (float*)d_out, nat);
}

// round 7
// speedup vs baseline: 3.5860x; 3.5860x over previous
#include <cuda_runtime.h>

#define NRAD  16
#define NOUT  144            // 16*(1 + 2*4)
#define L35   35
#define KT    20             // k-values per thread (35 padded to 40, 2 chunks)
#define MAXE   100000
#define MAXNAT 4096
#define ATOMS_PER_BLOCK 4
#define MBLOCK 128           // 4 warps = 4 atoms

__device__ int   g_segstart[MAXNAT + 1];
// g monomials, per edge 40 floats = 10 float4, interleaved by kg-half:
// float index e*40 + q*8 + kg*4 + m  <-  g[kg*20 + q*4 + m]   (k 35..39 = 0)
__device__ float g_gT[(size_t)MAXE * 40];

typedef unsigned long long ull;

__device__ __forceinline__ ull pack2(float x, float y) {
    ull r; asm("mov.b64 %0, {%1, %2};" : "=l"(r) : "f"(x), "f"(y)); return r;
}
__device__ __forceinline__ ull dup2(float x) {
    ull r; asm("mov.b64 %0, {%1, %1};" : "=l"(r) : "f"(x)); return r;
}
__device__ __forceinline__ void unpack2(ull p, float& x, float& y) {
    asm("mov.b64 {%0, %1}, %2;" : "=f"(x), "=f"(y) : "l"(p));
}
__device__ __forceinline__ void fma2(ull& d, ull a, ull b) {
    asm("fma.rn.f32x2 %0, %1, %2, %0;" : "+l"(d) : "l"(a), "l"(b));
}

// Prepass: monomials (smem-staged, coalesced out) + segment starts.
__global__ __launch_bounds__(256)
void prep_kernel(const float* __restrict__ rij, const int* __restrict__ fidx,
                 int E, int nat)
{
    __shared__ float sg[256][40];          // 40 KB

    constexpr int LXc[L35] = {0, 0,0,1, 0,0,0,1,1,2,
                              0,0,0,0,1,1,1,2,2,3,
                              0,0,0,0,0,1,1,1,1,2,2,2,3,3,4};
    constexpr int LYc[L35] = {0, 0,1,0, 0,1,2,0,1,0,
                              0,1,2,3,0,1,2,0,1,0,
                              0,1,2,3,4,0,1,2,3,0,1,2,0,1,0};
    constexpr int LZc[L35] = {0, 1,0,0, 2,1,0,1,0,0,
                              3,2,1,0,2,1,0,1,0,0,
                              4,3,2,1,0,3,2,1,0,2,1,0,1,0,0};
    constexpr float FNc[L35] = {1.f, 1.f,1.f,1.f,
                                1.f,2.f,1.f,2.f,2.f,1.f,
                                1.f,3.f,3.f,1.f,3.f,6.f,3.f,3.f,3.f,1.f,
                                1.f,4.f,6.f,4.f,1.f,4.f,12.f,12.f,4.f,
                                6.f,12.f,6.f,4.f,4.f,1.f};

    const int tid = threadIdx.x;
    const int e0  = blockIdx.x * 256;
    const int e   = e0 + tid;
    const int cnt = min(256, E - e0);

    if (e < E) {
        // segment starts (fidx sorted ascending)
        int cur  = fidx[e];
        int prev = (e == 0) ? -1 : fidx[e - 1];
        for (int a = prev + 1; a <= cur; a++) g_segstart[a] = e;
        if (e == E - 1)
            for (int a = cur + 1; a <= nat; a++) g_segstart[a] = E;

        float x = rij[e*3+0], y = rij[e*3+1], z = rij[e*3+2];
        float px[5], py[5], pz[5];
        px[0]=1.f; px[1]=x; px[2]=x*x; px[3]=px[2]*x; px[4]=px[2]*px[2];
        py[0]=1.f; py[1]=y; py[2]=y*y; py[3]=py[2]*y; py[4]=py[2]*py[2];
        pz[0]=1.f; pz[1]=z; pz[2]=z*z; pz[3]=pz[2]*z; pz[4]=pz[2]*pz[2];
        float g[40];
        #pragma unroll
        for (int k = 0; k < L35; k++)
            g[k] = FNc[k] * px[LXc[k]] * py[LYc[k]] * pz[LZc[k]];
        #pragma unroll
        for (int k = L35; k < 40; k++) g[k] = 0.f;
        // interleaved layout: [q][kg][m]
        #pragma unroll
        for (int q = 0; q < 5; q++)
            #pragma unroll
            for (int kg = 0; kg < 2; kg++)
                #pragma unroll
                for (int m = 0; m < 4; m++)
                    sg[tid][q*8 + kg*4 + m] = g[kg*20 + q*4 + m];
    }
    __syncthreads();

    // coalesced copy out: cnt*10 float4
    float4*       dst = (float4*)g_gT + (size_t)e0 * 10;
    const float4* src = (const float4*)sg;
    for (int i = tid; i < cnt * 10; i += 256)
        dst[i] = src[i];
}

__global__ __launch_bounds__(MBLOCK, 4)
void mbp_main(const float* __restrict__ radial,   // [E,16,5]
              const float* __restrict__ lamw,     // [2]
              float* __restrict__ out,            // [nat, NOUT]
              int nat)
{
    const int lane = threadIdx.x & 31;
    const int warp = threadIdx.x >> 5;
    const int j    = lane & 15;      // radial index
    const int kg   = lane >> 4;      // k-chunk half (0: k0-19, 1: k20-39)
    const int a    = blockIdx.x * ATOMS_PER_BLOCK + warp;
    if (a >= nat) return;            // uniform per warp

    const int start = g_segstart[a];
    const int end   = g_segstart[a + 1];

    // acc[i][c]: i=0..9 packs k-pair (2i, 2i+1) within this thread's chunk,
    // c = radial channel 0..3.  40 ull = 80 regs.
    ull acc[10][4];
    #pragma unroll
    for (int i = 0; i < 10; i++)
        #pragma unroll
        for (int c = 0; c < 4; c++) acc[i][c] = 0ull;
    float accR = 0.f;

    const float*  rp = radial + (size_t)start * 80 + j * 5;
    const float4* gp = (const float4*)g_gT + (size_t)start * 10 + kg;

    for (int e = start; e < end; e++) {
        float4 G0 = gp[0], G1 = gp[2], G2 = gp[4], G3 = gp[6], G4 = gp[8];
        float r0 = rp[0], r1 = rp[1], r2 = rp[2], r3 = rp[3];
        if (kg == 0) accR += rp[4];
        rp += 80;  gp += 10;
        ull d0 = dup2(r0), d1 = dup2(r1), d2 = dup2(r2), d3 = dup2(r3);
        {
            ull gA = pack2(G0.x, G0.y), gB = pack2(G0.z, G0.w);
            fma2(acc[0][0],gA,d0); fma2(acc[0][1],gA,d1); fma2(acc[0][2],gA,d2); fma2(acc[0][3],gA,d3);
            fma2(acc[1][0],gB,d0); fma2(acc[1][1],gB,d1); fma2(acc[1][2],gB,d2); fma2(acc[1][3],gB,d3);
        }
        {
            ull gA = pack2(G1.x, G1.y), gB = pack2(G1.z, G1.w);
            fma2(acc[2][0],gA,d0); fma2(acc[2][1],gA,d1); fma2(acc[2][2],gA,d2); fma2(acc[2][3],gA,d3);
            fma2(acc[3][0],gB,d0); fma2(acc[3][1],gB,d1); fma2(acc[3][2],gB,d2); fma2(acc[3][3],gB,d3);
        }
        {
            ull gA = pack2(G2.x, G2.y), gB = pack2(G2.z, G2.w);
            fma2(acc[4][0],gA,d0); fma2(acc[4][1],gA,d1); fma2(acc[4][2],gA,d2); fma2(acc[4][3],gA,d3);
            fma2(acc[5][0],gB,d0); fma2(acc[5][1],gB,d1); fma2(acc[5][2],gB,d2); fma2(acc[5][3],gB,d3);
        }
        {
            ull gA = pack2(G3.x, G3.y), gB = pack2(G3.z, G3.w);
            fma2(acc[6][0],gA,d0); fma2(acc[6][1],gA,d1); fma2(acc[6][2],gA,d2); fma2(acc[6][3],gA,d3);
            fma2(acc[7][0],gB,d0); fma2(acc[7][1],gB,d1); fma2(acc[7][2],gB,d2); fma2(acc[7][3],gB,d3);
        }
        {
            ull gA = pack2(G4.x, G4.y), gB = pack2(G4.z, G4.w);
            fma2(acc[8][0],gA,d0); fma2(acc[8][1],gA,d1); fma2(acc[8][2],gA,d2); fma2(acc[8][3],gA,d3);
            fma2(acc[9][0],gB,d0); fma2(acc[9][1],gB,d1); fma2(acc[9][2],gB,d2); fma2(acc[9][3],gB,d3);
        }
    }

    // ---- epilogue: group squares by lambda exponent, contract, reduce ----
    // chunk0 k-exponents: k0:0, k1-3:1, k4-9:2, k10-19:3 ; chunk1: all 4.
    // group-id per local k (chunk0): 0,1,1,1,2,2,2,2,2,2,3×10
    float gs[4][4];                  // [group][channel]
    #pragma unroll
    for (int g2 = 0; g2 < 4; g2++)
        #pragma unroll
        for (int c = 0; c < 4; c++) gs[g2][c] = 0.f;

    constexpr int GRP[20] = {0,1,1,1,2,2,2,2,2,2,3,3,3,3,3,3,3,3,3,3};
    if (kg == 0) {
        #pragma unroll
        for (int i = 0; i < 10; i++)
            #pragma unroll
            for (int c = 0; c < 4; c++) {
                float u, v; unpack2(acc[i][c], u, v);
                gs[GRP[2*i]][c]   += u * u;
                gs[GRP[2*i+1]][c] += v * v;
            }
    } else {
        #pragma unroll
        for (int i = 0; i < 10; i++)
            #pragma unroll
            for (int c = 0; c < 4; c++) {
                float u, v; unpack2(acc[i][c], u, v);
                gs[0][c] += u * u + v * v;     // all lambda^4 (pads hold 0)
            }
    }

    float l0 = lamw[0], l1 = lamw[1];
    float p[4][2];
    if (kg == 0) {
        float l0b = l0*l0, l0c = l0b*l0;
        float l1b = l1*l1, l1c = l1b*l1;
        #pragma unroll
        for (int c = 0; c < 4; c++) {
            p[c][0] = gs[0][c] + gs[1][c]*l0 + gs[2][c]*l0b + gs[3][c]*l0c;
            p[c][1] = gs[0][c] + gs[1][c]*l1 + gs[2][c]*l1b + gs[3][c]*l1c;
        }
    } else {
        float l0d = (l0*l0)*(l0*l0);
        float l1d = (l1*l1)*(l1*l1);
        #pragma unroll
        for (int c = 0; c < 4; c++) {
            p[c][0] = gs[0][c] * l0d;
            p[c][1] = gs[0][c] * l1d;
        }
    }

    // combine the two kg halves
    #pragma unroll
    for (int c = 0; c < 4; c++)
        #pragma unroll
        for (int l = 0; l < 2; l++)
            p[c][l] += __shfl_xor_sync(0xffffffffu, p[c][l], 16);

    if (kg == 0) {
        float* orow = out + (size_t)a * NOUT;
        orow[j] = accR;
        #pragma unroll
        for (int c = 0; c < 4; c++) {
            float scale = __int_as_float(0x3F800000 - (c << 23));   // 2^-c
            orow[16 + c*32 + j*2 + 0] = p[c][0] * scale;
            orow[16 + c*32 + j*2 + 1] = p[c][1] * scale;
        }
    }
}

extern "C" void kernel_launch(void* const* d_in, const int* in_sizes, int n_in,
                              void* d_out, int out_size)
{
    const float* rij    = (const float*)d_in[0];   // [E,3]
    const float* radial = (const float*)d_in[1];   // [E,16,5]
    const float* lamw   = (const float*)d_in[2];   // [2]
    const int*   fidx   = (const int*)  d_in[4];   // [E] sorted

    const int E   = in_sizes[0] / 3;
    const int nat = out_size / NOUT;

    prep_kernel<<<(E + 255) / 256, 256>>>(rij, fidx, E, nat);
    mbp_main<<<(nat + ATOMS_PER_BLOCK - 1) / ATOMS_PER_BLOCK, MBLOCK>>>(
        radial, lamw, (float*)d_out, nat);
}